// round 4
// baseline (speedup 1.0000x reference)
#include <cuda_runtime.h>
#include <math.h>

#define NMAX 100000
#define FD   128

// ---- static device scratch (no allocations allowed) ----
__device__ float g_xn[(size_t)NMAX * FD];   // projected/scaled features (gather source)
__device__ float g_agg[(size_t)NMAX * FD];  // scatter-add accumulator
__device__ int   g_deg_out[NMAX];
__device__ int   g_deg_in[NMAX];
__device__ float g_norm_src[NMAX];
__device__ float g_norm_dst[NMAX];

// ------------------------------------------------------------------
// small kernels
// ------------------------------------------------------------------
__global__ void zero_deg_kernel(int N) {
    int i = blockIdx.x * blockDim.x + threadIdx.x;
    if (i < N) { g_deg_out[i] = 0; g_deg_in[i] = 0; }
}

__global__ void deg_kernel(const int* __restrict__ src, const int* __restrict__ dst, int E) {
    int i = blockIdx.x * blockDim.x + threadIdx.x;
    int stride = gridDim.x * blockDim.x;
    for (; i < E; i += stride) {
        atomicAdd(&g_deg_out[src[i]], 1);
        atomicAdd(&g_deg_in[dst[i]], 1);
    }
}

__global__ void norms_kernel(int N) {
    int i = blockIdx.x * blockDim.x + threadIdx.x;
    if (i < N) {
        int dout = g_deg_out[i];
        int din  = g_deg_in[i];
        g_norm_src[i] = rsqrtf((float)(dout > 1 ? dout : 1));
        g_norm_dst[i] = rsqrtf((float)(din  > 1 ? din  : 1));
    }
}

__global__ void zero_agg_kernel(int n4) {   // n4 = N*32 float4s
    int i = blockIdx.x * blockDim.x + threadIdx.x;
    int stride = gridDim.x * blockDim.x;
    float4 z = make_float4(0.f, 0.f, 0.f, 0.f);
    float4* p = reinterpret_cast<float4*>(g_agg);
    for (; i < n4; i += stride) p[i] = z;
}

// ------------------------------------------------------------------
// GEMM: out(g_xn)[r,:] = prologue(A[r,:]) @ W    (M=N, N=128, K=128)
// MODE 0: prologue = A[r,:] * norm_src[r]                         (A = feature)
// MODE 1: prologue = relu(g_agg[r,:]*norm_dst[r] + bias) * norm_src[r]
// Tiles: BM=64, BN=128, BK=32; 256 threads; 4x8 micro-tile/thread.
// ------------------------------------------------------------------
template <int MODE>
__global__ void __launch_bounds__(256)
gemm_kernel(const float* __restrict__ A,
            const float* __restrict__ W,
            const float* __restrict__ bias,
            int N)
{
    __shared__ float As[64][33];
    __shared__ float Bs[32][128];

    const int tid  = threadIdx.x;
    const int row0 = blockIdx.x * 64;
    const int trow = tid >> 4;          // 0..15
    const int tcol = tid & 15;          // 0..15
    const int m0   = trow * 4;
    const int n0   = tcol * 8;

    const float* Ain = (MODE == 0) ? A : g_agg;

    float acc[4][8];
#pragma unroll
    for (int i = 0; i < 4; i++)
#pragma unroll
        for (int j = 0; j < 8; j++) acc[i][j] = 0.f;

    for (int kb = 0; kb < FD; kb += 32) {
        // --- load A tile (64x32), 2 float4 per thread, with fused prologue ---
#pragma unroll
        for (int i = 0; i < 2; i++) {
            int f  = tid + i * 256;     // float4 index within tile
            int m  = f >> 3;            // 0..63
            int k4 = f & 7;             // 0..7
            int r  = row0 + m;
            float4 v = make_float4(0.f, 0.f, 0.f, 0.f);
            if (r < N) {
                v = *reinterpret_cast<const float4*>(Ain + (size_t)r * FD + kb + k4 * 4);
                if (MODE == 0) {
                    float s = g_norm_src[r];
                    v.x *= s; v.y *= s; v.z *= s; v.w *= s;
                } else {
                    float nd = g_norm_dst[r];
                    float ns = g_norm_src[r];
                    float4 b = *reinterpret_cast<const float4*>(bias + kb + k4 * 4);
                    v.x = fmaxf(fmaf(v.x, nd, b.x), 0.f) * ns;
                    v.y = fmaxf(fmaf(v.y, nd, b.y), 0.f) * ns;
                    v.z = fmaxf(fmaf(v.z, nd, b.z), 0.f) * ns;
                    v.w = fmaxf(fmaf(v.w, nd, b.w), 0.f) * ns;
                }
            }
            As[m][k4 * 4 + 0] = v.x;
            As[m][k4 * 4 + 1] = v.y;
            As[m][k4 * 4 + 2] = v.z;
            As[m][k4 * 4 + 3] = v.w;
        }
        // --- load B tile (32x128), 4 float4 per thread ---
#pragma unroll
        for (int i = 0; i < 4; i++) {
            int f  = tid + i * 256;
            int k  = f >> 5;            // 0..31
            int n4 = f & 31;            // 0..31
            *reinterpret_cast<float4*>(&Bs[k][n4 * 4]) =
                *reinterpret_cast<const float4*>(W + (size_t)(kb + k) * FD + n4 * 4);
        }
        __syncthreads();

#pragma unroll
        for (int k = 0; k < 32; k++) {
            float a[4];
#pragma unroll
            for (int i = 0; i < 4; i++) a[i] = As[m0 + i][k];
            float b[8];
            *reinterpret_cast<float4*>(&b[0]) = *reinterpret_cast<float4*>(&Bs[k][n0]);
            *reinterpret_cast<float4*>(&b[4]) = *reinterpret_cast<float4*>(&Bs[k][n0 + 4]);
#pragma unroll
            for (int i = 0; i < 4; i++)
#pragma unroll
                for (int j = 0; j < 8; j++)
                    acc[i][j] = fmaf(a[i], b[j], acc[i][j]);
        }
        __syncthreads();
    }

#pragma unroll
    for (int i = 0; i < 4; i++) {
        int r = row0 + m0 + i;
        if (r < N) {
            float4 o0 = make_float4(acc[i][0], acc[i][1], acc[i][2], acc[i][3]);
            float4 o1 = make_float4(acc[i][4], acc[i][5], acc[i][6], acc[i][7]);
            *reinterpret_cast<float4*>(g_xn + (size_t)r * FD + n0)     = o0;
            *reinterpret_cast<float4*>(g_xn + (size_t)r * FD + n0 + 4) = o1;
        }
    }
}

// ------------------------------------------------------------------
// edge scatter: g_agg[dst[e],:] += g_xn[src[e],:]
// 32 edges batched per warp iteration (coalesced index loads + shfl
// broadcast). 128 floats/edge = 32 lanes x float4.
// red.global.add.v4.f32: one L2 reduction op per 16B.
// Full batches take the predicate-free fast path; only the single tail
// batch (e >= E possible) pays per-edge predication.
// ------------------------------------------------------------------
__global__ void __launch_bounds__(256)
scatter_kernel(const int* __restrict__ src, const int* __restrict__ dst, int E)
{
    const int lane   = threadIdx.x & 31;
    const int gwarp  = (blockIdx.x * blockDim.x + threadIdx.x) >> 5;
    const int nwarps = (gridDim.x * blockDim.x) >> 5;
    const int nfull  = E >> 5;                 // batches with all 32 edges valid
    const int nbatch = (E + 31) >> 5;

    for (int b = gwarp; b < nbatch; b += nwarps) {
        int e = b * 32 + lane;
        if (b < nfull) {
            int s = src[e];
            int d = dst[e];
#pragma unroll
            for (int j = 0; j < 32; j++) {
                int sj = __shfl_sync(0xffffffffu, s, j);
                int dj = __shfl_sync(0xffffffffu, d, j);
                float4 v = *reinterpret_cast<const float4*>(g_xn + (size_t)sj * FD + lane * 4);
                float* p = g_agg + (size_t)dj * FD + lane * 4;
                asm volatile("red.global.add.v4.f32 [%0], {%1, %2, %3, %4};"
                             :: "l"(p), "f"(v.x), "f"(v.y), "f"(v.z), "f"(v.w)
                             : "memory");
            }
        } else {
            int s = -1, d = -1;
            if (e < E) { s = src[e]; d = dst[e]; }
#pragma unroll
            for (int j = 0; j < 32; j++) {
                int sj = __shfl_sync(0xffffffffu, s, j);
                int dj = __shfl_sync(0xffffffffu, d, j);
                if (sj >= 0) {
                    float4 v = *reinterpret_cast<const float4*>(g_xn + (size_t)sj * FD + lane * 4);
                    float* p = g_agg + (size_t)dj * FD + lane * 4;
                    asm volatile("red.global.add.v4.f32 [%0], {%1, %2, %3, %4};"
                                 :: "l"(p), "f"(v.x), "f"(v.y), "f"(v.z), "f"(v.w)
                                 : "memory");
                }
            }
        }
    }
}

// ------------------------------------------------------------------
// final epilogue: out[r,:] = g_agg[r,:] * norm_dst[r] + b2
// ------------------------------------------------------------------
__global__ void epilogue_kernel(const float* __restrict__ b2, float* __restrict__ out, int N)
{
    int i = blockIdx.x * blockDim.x + threadIdx.x;   // over N*32 float4
    int total = N * 32;
    if (i < total) {
        int r  = i >> 5;
        int c4 = i & 31;
        float nd = g_norm_dst[r];
        float4 a = reinterpret_cast<const float4*>(g_agg)[i];
        float4 b = reinterpret_cast<const float4*>(b2)[c4];
        float4 o = make_float4(fmaf(a.x, nd, b.x), fmaf(a.y, nd, b.y),
                               fmaf(a.z, nd, b.z), fmaf(a.w, nd, b.w));
        reinterpret_cast<float4*>(out)[i] = o;
    }
}

// ------------------------------------------------------------------
extern "C" void kernel_launch(void* const* d_in, const int* in_sizes, int n_in,
                              void* d_out, int out_size)
{
    const float* feature = (const float*)d_in[0];
    const int*   src     = (const int*)  d_in[1];
    const int*   dst     = (const int*)  d_in[2];
    const float* W1      = (const float*)d_in[3];
    const float* b1      = (const float*)d_in[4];
    const float* W2      = (const float*)d_in[5];
    const float* b2      = (const float*)d_in[6];
    float*       out     = (float*)d_out;

    const int N = in_sizes[0] / FD;
    const int E = in_sizes[1];

    const int T = 256;
    const int PERSIST = 1184;                 // 148 SMs x 8 blocks
    const int gridN   = (N + T - 1) / T;
    const int gridM   = (N + 63) / 64;
    const int gridE4  = (N * 32 + T - 1) / T;

    // degree norms
    zero_deg_kernel<<<gridN, T>>>(N);
    deg_kernel<<<PERSIST, T>>>(src, dst, E);
    norms_kernel<<<gridN, T>>>(N);

    // layer 1: xn = (feature * norm_src) @ W1 ; agg = scatter-add(xn[src] -> dst)
    gemm_kernel<0><<<gridM, T>>>(feature, W1, nullptr, N);
    zero_agg_kernel<<<PERSIST, T>>>(N * 32);
    scatter_kernel<<<PERSIST, T>>>(src, dst, E);

    // layer 2: xn = (relu(agg*norm_dst + b1) * norm_src) @ W2 ; agg = scatter-add
    gemm_kernel<1><<<gridM, T>>>(nullptr, W2, b1, N);
    zero_agg_kernel<<<PERSIST, T>>>(N * 32);
    scatter_kernel<<<PERSIST, T>>>(src, dst, E);

    // out = agg*norm_dst + b2
    epilogue_kernel<<<gridE4, T>>>(b2, out, N);
}

// round 5
// speedup vs baseline: 1.0044x; 1.0044x over previous
#include <cuda_runtime.h>
#include <math.h>

#define NMAX 100000
#define FD   128

// ---- static device scratch (no allocations allowed) ----
__device__ float g_xn[(size_t)NMAX * FD];   // projected/scaled features (gather source)
__device__ float g_agg[(size_t)NMAX * FD];  // scatter-add accumulator
__device__ int   g_deg_out[NMAX];
__device__ int   g_deg_in[NMAX];
__device__ float g_norm_src[NMAX];
__device__ float g_norm_dst[NMAX];

// ------------------------------------------------------------------
// small kernels
// ------------------------------------------------------------------
__global__ void zero_deg_kernel(int N) {
    int i = blockIdx.x * blockDim.x + threadIdx.x;
    if (i < N) { g_deg_out[i] = 0; g_deg_in[i] = 0; }
}

__global__ void deg_kernel(const int* __restrict__ src, const int* __restrict__ dst, int E) {
    int i = blockIdx.x * blockDim.x + threadIdx.x;
    int stride = gridDim.x * blockDim.x;
    for (; i < E; i += stride) {
        atomicAdd(&g_deg_out[src[i]], 1);
        atomicAdd(&g_deg_in[dst[i]], 1);
    }
}

__global__ void norms_kernel(int N) {
    int i = blockIdx.x * blockDim.x + threadIdx.x;
    if (i < N) {
        int dout = g_deg_out[i];
        int din  = g_deg_in[i];
        g_norm_src[i] = rsqrtf((float)(dout > 1 ? dout : 1));
        g_norm_dst[i] = rsqrtf((float)(din  > 1 ? din  : 1));
    }
}

__global__ void zero_agg_kernel(int n4) {   // n4 = N*32 float4s
    int i = blockIdx.x * blockDim.x + threadIdx.x;
    int stride = gridDim.x * blockDim.x;
    float4 z = make_float4(0.f, 0.f, 0.f, 0.f);
    float4* p = reinterpret_cast<float4*>(g_agg);
    for (; i < n4; i += stride) p[i] = z;
}

// ------------------------------------------------------------------
// GEMM: out(g_xn)[r,:] = prologue(A[r,:]) @ W    (M=N, N=128, K=128)
// MODE 0: prologue = A[r,:] * norm_src[r]                         (A = feature)
// MODE 1: prologue = relu(g_agg[r,:]*norm_dst[r] + bias) * norm_src[r]
// Tiles: BM=64, BN=128, BK=32; 256 threads; 4x8 micro-tile/thread.
// ------------------------------------------------------------------
template <int MODE>
__global__ void __launch_bounds__(256)
gemm_kernel(const float* __restrict__ A,
            const float* __restrict__ W,
            const float* __restrict__ bias,
            int N)
{
    __shared__ float As[64][33];
    __shared__ float Bs[32][128];

    const int tid  = threadIdx.x;
    const int row0 = blockIdx.x * 64;
    const int trow = tid >> 4;          // 0..15
    const int tcol = tid & 15;          // 0..15
    const int m0   = trow * 4;
    const int n0   = tcol * 8;

    const float* Ain = (MODE == 0) ? A : g_agg;

    float acc[4][8];
#pragma unroll
    for (int i = 0; i < 4; i++)
#pragma unroll
        for (int j = 0; j < 8; j++) acc[i][j] = 0.f;

    for (int kb = 0; kb < FD; kb += 32) {
        // --- load A tile (64x32), 2 float4 per thread, with fused prologue ---
#pragma unroll
        for (int i = 0; i < 2; i++) {
            int f  = tid + i * 256;     // float4 index within tile
            int m  = f >> 3;            // 0..63
            int k4 = f & 7;             // 0..7
            int r  = row0 + m;
            float4 v = make_float4(0.f, 0.f, 0.f, 0.f);
            if (r < N) {
                v = *reinterpret_cast<const float4*>(Ain + (size_t)r * FD + kb + k4 * 4);
                if (MODE == 0) {
                    float s = g_norm_src[r];
                    v.x *= s; v.y *= s; v.z *= s; v.w *= s;
                } else {
                    float nd = g_norm_dst[r];
                    float ns = g_norm_src[r];
                    float4 b = *reinterpret_cast<const float4*>(bias + kb + k4 * 4);
                    v.x = fmaxf(fmaf(v.x, nd, b.x), 0.f) * ns;
                    v.y = fmaxf(fmaf(v.y, nd, b.y), 0.f) * ns;
                    v.z = fmaxf(fmaf(v.z, nd, b.z), 0.f) * ns;
                    v.w = fmaxf(fmaf(v.w, nd, b.w), 0.f) * ns;
                }
            }
            As[m][k4 * 4 + 0] = v.x;
            As[m][k4 * 4 + 1] = v.y;
            As[m][k4 * 4 + 2] = v.z;
            As[m][k4 * 4 + 3] = v.w;
        }
        // --- load B tile (32x128), 4 float4 per thread ---
#pragma unroll
        for (int i = 0; i < 4; i++) {
            int f  = tid + i * 256;
            int k  = f >> 5;            // 0..31
            int n4 = f & 31;            // 0..31
            *reinterpret_cast<float4*>(&Bs[k][n4 * 4]) =
                *reinterpret_cast<const float4*>(W + (size_t)(kb + k) * FD + n4 * 4);
        }
        __syncthreads();

#pragma unroll
        for (int k = 0; k < 32; k++) {
            float a[4];
#pragma unroll
            for (int i = 0; i < 4; i++) a[i] = As[m0 + i][k];
            float b[8];
            *reinterpret_cast<float4*>(&b[0]) = *reinterpret_cast<float4*>(&Bs[k][n0]);
            *reinterpret_cast<float4*>(&b[4]) = *reinterpret_cast<float4*>(&Bs[k][n0 + 4]);
#pragma unroll
            for (int i = 0; i < 4; i++)
#pragma unroll
                for (int j = 0; j < 8; j++)
                    acc[i][j] = fmaf(a[i], b[j], acc[i][j]);
        }
        __syncthreads();
    }

#pragma unroll
    for (int i = 0; i < 4; i++) {
        int r = row0 + m0 + i;
        if (r < N) {
            float4 o0 = make_float4(acc[i][0], acc[i][1], acc[i][2], acc[i][3]);
            float4 o1 = make_float4(acc[i][4], acc[i][5], acc[i][6], acc[i][7]);
            *reinterpret_cast<float4*>(g_xn + (size_t)r * FD + n0)     = o0;
            *reinterpret_cast<float4*>(g_xn + (size_t)r * FD + n0 + 4) = o1;
        }
    }
}

// ------------------------------------------------------------------
// edge scatter: g_agg[dst[e],:] += g_xn[src[e],:]
// 32 edges batched per warp iteration (coalesced index loads + shfl
// broadcast). 128 floats/edge = 32 lanes x float4.
// red.global.add.v4.f32: one L2 reduction op per 16B.
// Full batches take the predicate-free fast path; only the single tail
// batch (e >= E possible) pays per-edge predication.
// ------------------------------------------------------------------
__global__ void __launch_bounds__(256)
scatter_kernel(const int* __restrict__ src, const int* __restrict__ dst, int E)
{
    const int lane   = threadIdx.x & 31;
    const int gwarp  = (blockIdx.x * blockDim.x + threadIdx.x) >> 5;
    const int nwarps = (gridDim.x * blockDim.x) >> 5;
    const int nfull  = E >> 5;                 // batches with all 32 edges valid
    const int nbatch = (E + 31) >> 5;

    for (int b = gwarp; b < nbatch; b += nwarps) {
        int e = b * 32 + lane;
        if (b < nfull) {
            int s = src[e];
            int d = dst[e];
#pragma unroll
            for (int j = 0; j < 32; j++) {
                int sj = __shfl_sync(0xffffffffu, s, j);
                int dj = __shfl_sync(0xffffffffu, d, j);
                float4 v = *reinterpret_cast<const float4*>(g_xn + (size_t)sj * FD + lane * 4);
                float* p = g_agg + (size_t)dj * FD + lane * 4;
                asm volatile("red.global.add.v4.f32 [%0], {%1, %2, %3, %4};"
                             :: "l"(p), "f"(v.x), "f"(v.y), "f"(v.z), "f"(v.w)
                             : "memory");
            }
        } else {
            int s = -1, d = -1;
            if (e < E) { s = src[e]; d = dst[e]; }
#pragma unroll
            for (int j = 0; j < 32; j++) {
                int sj = __shfl_sync(0xffffffffu, s, j);
                int dj = __shfl_sync(0xffffffffu, d, j);
                if (sj >= 0) {
                    float4 v = *reinterpret_cast<const float4*>(g_xn + (size_t)sj * FD + lane * 4);
                    float* p = g_agg + (size_t)dj * FD + lane * 4;
                    asm volatile("red.global.add.v4.f32 [%0], {%1, %2, %3, %4};"
                                 :: "l"(p), "f"(v.x), "f"(v.y), "f"(v.z), "f"(v.w)
                                 : "memory");
                }
            }
        }
    }
}

// ------------------------------------------------------------------
// final epilogue: out[r,:] = g_agg[r,:] * norm_dst[r] + b2
// ------------------------------------------------------------------
__global__ void epilogue_kernel(const float* __restrict__ b2, float* __restrict__ out, int N)
{
    int i = blockIdx.x * blockDim.x + threadIdx.x;   // over N*32 float4
    int total = N * 32;
    if (i < total) {
        int r  = i >> 5;
        int c4 = i & 31;
        float nd = g_norm_dst[r];
        float4 a = reinterpret_cast<const float4*>(g_agg)[i];
        float4 b = reinterpret_cast<const float4*>(b2)[c4];
        float4 o = make_float4(fmaf(a.x, nd, b.x), fmaf(a.y, nd, b.y),
                               fmaf(a.z, nd, b.z), fmaf(a.w, nd, b.w));
        reinterpret_cast<float4*>(out)[i] = o;
    }
}

// ------------------------------------------------------------------
extern "C" void kernel_launch(void* const* d_in, const int* in_sizes, int n_in,
                              void* d_out, int out_size)
{
    const float* feature = (const float*)d_in[0];
    const int*   src     = (const int*)  d_in[1];
    const int*   dst     = (const int*)  d_in[2];
    const float* W1      = (const float*)d_in[3];
    const float* b1      = (const float*)d_in[4];
    const float* W2      = (const float*)d_in[5];
    const float* b2      = (const float*)d_in[6];
    float*       out     = (float*)d_out;

    const int N = in_sizes[0] / FD;
    const int E = in_sizes[1];

    const int T = 256;
    const int PERSIST = 1184;                 // 148 SMs x 8 blocks
    const int gridN   = (N + T - 1) / T;
    const int gridM   = (N + 63) / 64;
    const int gridE4  = (N * 32 + T - 1) / T;

    // degree norms
    zero_deg_kernel<<<gridN, T>>>(N);
    deg_kernel<<<PERSIST, T>>>(src, dst, E);
    norms_kernel<<<gridN, T>>>(N);

    // layer 1: xn = (feature * norm_src) @ W1 ; agg = scatter-add(xn[src] -> dst)
    gemm_kernel<0><<<gridM, T>>>(feature, W1, nullptr, N);
    zero_agg_kernel<<<PERSIST, T>>>(N * 32);
    scatter_kernel<<<PERSIST, T>>>(src, dst, E);

    // layer 2: xn = (relu(agg*norm_dst + b1) * norm_src) @ W2 ; agg = scatter-add
    gemm_kernel<1><<<gridM, T>>>(nullptr, W2, b1, N);
    zero_agg_kernel<<<PERSIST, T>>>(N * 32);
    scatter_kernel<<<PERSIST, T>>>(src, dst, E);

    // out = agg*norm_dst + b2
    epilogue_kernel<<<gridE4, T>>>(b2, out, N);
}